// round 5
// baseline (speedup 1.0000x reference)
#include <cuda_runtime.h>
#include <cuda_bf16.h>
#include <cstdint>

// ====================== mma.sync helpers ======================
__device__ __forceinline__ uint32_t smem_to_u32(const void* smem_ptr) {
    uint32_t addr;
    asm("{ .reg .u64 tmp; cvta.to.shared.u64 tmp, %1; cvt.u32.u64 %0, tmp; }"
        : "=r"(addr) : "l"(smem_ptr));
    return addr;
}
__device__ __forceinline__ void ldsm_x4(uint32_t* r, uint32_t addr) {
    asm volatile("ldmatrix.sync.aligned.m8n8.x4.shared.b16 {%0,%1,%2,%3}, [%4];"
        : "=r"(r[0]), "=r"(r[1]), "=r"(r[2]), "=r"(r[3]) : "r"(addr));
}
__device__ __forceinline__ void ldsm_x2(uint32_t* r, uint32_t addr) {
    asm volatile("ldmatrix.sync.aligned.m8n8.x2.shared.b16 {%0,%1}, [%2];"
        : "=r"(r[0]), "=r"(r[1]) : "r"(addr));
}
__device__ __forceinline__ void mma_16816(float* c, const uint32_t* a, const uint32_t* b) {
    asm volatile("mma.sync.aligned.m16n8k16.row.col.f32.bf16.bf16.f32 "
        "{%0,%1,%2,%3}, {%4,%5,%6,%7}, {%8,%9}, {%0,%1,%2,%3};"
        : "+f"(c[0]), "+f"(c[1]), "+f"(c[2]), "+f"(c[3])
        : "r"(a[0]), "r"(a[1]), "r"(a[2]), "r"(a[3]), "r"(b[0]), "r"(b[1]));
}
#define CP_ASYNC16(dst, src) \
    asm volatile("cp.async.cg.shared.global [%0], [%1], 16;" :: "r"(dst), "l"(src))
#define CP_COMMIT() asm volatile("cp.async.commit_group;" ::: "memory")
#define CP_WAIT(n)  asm volatile("cp.async.wait_group %0;" :: "n"(n) : "memory")

// ====================== static scratch ======================
__device__ float z_buf  [64 * 512 * 784];
__device__ float g_stats[1024];

__device__ __nv_bfloat16 wcat_hi[768 * 512], wcat_lo[768 * 512];
__device__ __nv_bfloat16 wW_hi [512 * 256],  wW_lo [512 * 256];
__device__ __nv_bfloat16 xt_hi [64 * 784 * 512], xt_lo[64 * 784 * 512];   // x^T per img
__device__ __nv_bfloat16 thetat_hi[8 * 6272 * 256], thetat_lo[8 * 6272 * 256]; // [b][t][ci] VIEW
__device__ __nv_bfloat16 yt_hi [64 * 784 * 256], yt_lo[64 * 784 * 256];   // [img][s][c] conv
__device__ __nv_bfloat16 gp_hi [8 * 256 * 1568], gp_lo[8 * 256 * 1568];   // [b][ci][p] VIEW
__device__ __nv_bfloat16 pp_hi [8 * 256 * 1568], pp_lo[8 * 256 * 1568];   // [b][ci][p] VIEW
__device__ __nv_bfloat16 Mt_hi [8 * 256 * 256],  Mt_lo[8 * 256 * 256];    // M^T [b][cg][ci]

__device__ __forceinline__ void split_store(float v, __nv_bfloat16* hi, __nv_bfloat16* lo,
                                            size_t idx) {
    __nv_bfloat16 h = __float2bfloat16(v);
    hi[idx] = h;
    lo[idx] = __float2bfloat16(v - __bfloat162float(h));
}

// ====================== split/convert kernels ======================
__global__ __launch_bounds__(256) void split_w_kernel(
    const float* __restrict__ wth, const float* __restrict__ wg,
    const float* __restrict__ wph, const float* __restrict__ wW)
{
    int i = blockIdx.x * 256 + threadIdx.x;       // 0..524287
    if (i < 393216) {
        int r = i >> 9, k = i & 511;
        const float* w = (r < 256) ? wth : (r < 512) ? wg : wph;
        split_store(w[(r & 255) * 512 + k], wcat_hi, wcat_lo, i);
    } else {
        int j = i - 393216;
        split_store(wW[j], wW_hi, wW_lo, j);
    }
}

__global__ __launch_bounds__(256) void split_x_kernel(const float* __restrict__ x)
{
    __shared__ float t[16][17];
    int img = blockIdx.z;
    int c0 = blockIdx.y * 16, s0 = blockIdx.x * 16;
    const float* src = x + ((size_t)img * 512 + c0) * 784 + s0;
    t[threadIdx.y][threadIdx.x] = src[threadIdx.y * 784 + threadIdx.x];
    __syncthreads();
    float v = t[threadIdx.x][threadIdx.y];
    size_t dst = ((size_t)img * 784 + s0 + threadIdx.y) * 512 + c0 + threadIdx.x;
    split_store(v, xt_hi, xt_lo, dst);
}

// ====================== projection GEMM (theta|g|phi) + fused pool/view-remap ======
// Out[768, 784] per img = Wcat[768,512] @ Xt[784,512]^T + bias. CTA 128x112, BK=32.
// View mapping (reshape [64,256,S] -> [8,256,8S]):
//   ci_view = (img&7)*32 + (c_conv>>3);  pos_view = (c_conv&7)*S + s   (S=784 / 196)
static constexpr int TC_STAGES = 4;
static constexpr int STAGE_ELEMS = 480 * 40;
static constexpr int TC_SMEM = TC_STAGES * STAGE_ELEMS * 2;   // 153600

__global__ __launch_bounds__(256, 1) void proj_gemm_mma(
    const float* __restrict__ bth, const float* __restrict__ bg,
    const float* __restrict__ bph)
{
    constexpr int KDIM = 512;
    constexpr int KITERS = KDIM / 32;
    extern __shared__ __align__(128) __nv_bfloat16 smem[];
    const uint32_t smem_base = smem_to_u32(smem);

    const int tid = threadIdx.x;
    const int lane = tid & 31;
    const int wid = tid >> 5;
    const int warp_m = wid & 3;
    const int warp_n = wid >> 2;
    const int img = blockIdx.z;
    const int m0 = blockIdx.y * 128;       // 0..640
    const int n0 = blockIdx.x * 112;

    const __nv_bfloat16* A_hi = wcat_hi + (size_t)m0 * KDIM;
    const __nv_bfloat16* A_lo = wcat_lo + (size_t)m0 * KDIM;
    const __nv_bfloat16* B_hi = xt_hi + ((size_t)img * 784 + n0) * KDIM;
    const __nv_bfloat16* B_lo = xt_lo + ((size_t)img * 784 + n0) * KDIM;

    auto load_stage = [&](int st, int k0) {
        const uint32_t sb = smem_base + (uint32_t)(st * STAGE_ELEMS * 2);
        for (int i = tid; i < 1920; i += 256) {
            int row, kc;
            const __nv_bfloat16* src;
            int dst_row;
            if (i < 1024) {
                int d = i >> 9, j = i & 511;
                row = j >> 2; kc = j & 3;
                src = (d ? A_lo : A_hi) + (size_t)row * KDIM + k0 + kc * 8;
                dst_row = d * 128 + row;
            } else {
                int j = i - 1024;
                int d = (j >= 448); if (d) j -= 448;
                row = j >> 2; kc = j & 3;
                src = (d ? B_lo : B_hi) + (size_t)row * KDIM + k0 + kc * 8;
                dst_row = 256 + d * 112 + row;
            }
            uint32_t dst = sb + (uint32_t)((dst_row * 40 + kc * 8) * 2);
            CP_ASYNC16(dst, src);
        }
    };

    float acc[2][7][4];
#pragma unroll
    for (int mi = 0; mi < 2; mi++)
#pragma unroll
        for (int ni = 0; ni < 7; ni++)
#pragma unroll
            for (int r = 0; r < 4; r++) acc[mi][ni][r] = 0.f;

#pragma unroll
    for (int s = 0; s < TC_STAGES - 1; s++) { load_stage(s, s * 32); CP_COMMIT(); }

    const int a_row = lane & 15, a_kh = lane >> 4;
    const int b_row = lane & 7,  b_kh = (lane >> 3) & 1;

    for (int it = 0; it < KITERS; it++) {
        CP_WAIT(TC_STAGES - 2);
        __syncthreads();
        if (it + TC_STAGES - 1 < KITERS)
            load_stage((it + TC_STAGES - 1) % TC_STAGES, (it + TC_STAGES - 1) * 32);
        CP_COMMIT();

        const uint32_t sb = smem_base + (uint32_t)((it % TC_STAGES) * STAGE_ELEMS * 2);
#pragma unroll
        for (int ks = 0; ks < 2; ks++) {
            uint32_t af[2][2][4];
#pragma unroll
            for (int d = 0; d < 2; d++)
#pragma unroll
                for (int mi = 0; mi < 2; mi++) {
                    int r = d * 128 + warp_m * 32 + mi * 16 + a_row;
                    int c = ks * 16 + a_kh * 8;
                    ldsm_x4(af[d][mi], sb + (uint32_t)((r * 40 + c) * 2));
                }
            uint32_t bf[2][7][2];
#pragma unroll
            for (int d = 0; d < 2; d++)
#pragma unroll
                for (int ni = 0; ni < 7; ni++) {
                    int r = 256 + d * 112 + warp_n * 56 + ni * 8 + b_row;
                    int c = ks * 16 + b_kh * 8;
                    ldsm_x2(bf[d][ni], sb + (uint32_t)((r * 40 + c) * 2));
                }
#pragma unroll
            for (int mi = 0; mi < 2; mi++)
#pragma unroll
                for (int ni = 0; ni < 7; ni++) {
                    mma_16816(acc[mi][ni], af[0][mi], bf[0][ni]);
                    mma_16816(acc[mi][ni], af[0][mi], bf[1][ni]);
                    mma_16816(acc[mi][ni], af[1][mi], bf[0][ni]);
                }
        }
        __syncthreads();
    }

    // ---- stage C + bias into SMEM fp32 [128 ch][pitch 113 spatial] ----
    const int region = m0 >> 8;             // 0 theta, 1 g, 2 phi
    const int mloc = m0 & 255;              // 0 or 128
    const float* bias = (region == 0) ? bth : (region == 1) ? bg : bph;
    float* smf = reinterpret_cast<float*>(smem);

#pragma unroll
    for (int mi = 0; mi < 2; mi++) {
        int r0 = warp_m * 32 + mi * 16 + (lane >> 2);
        float bv0 = bias[mloc + r0];
        float bv1 = bias[mloc + r0 + 8];
#pragma unroll
        for (int ni = 0; ni < 7; ni++) {
            int col = warp_n * 56 + ni * 8 + (lane & 3) * 2;
            smf[r0 * 113 + col]           = acc[mi][ni][0] + bv0;
            smf[r0 * 113 + col + 1]       = acc[mi][ni][1] + bv0;
            smf[(r0 + 8) * 113 + col]     = acc[mi][ni][2] + bv1;
            smf[(r0 + 8) * 113 + col + 1] = acc[mi][ni][3] + bv1;
        }
    }
    __syncthreads();

    const int b = img >> 3, r = img & 7;
    const int cibase = r * 32 + (mloc >> 3);

    if (region == 0) {
        // theta -> thetat[b][t][ci], t = u*784 + (n0+sl), ci = cibase + q
        for (int item = tid; item < 896; item += 256) {
            int sl = item >> 3, u = item & 7;
            int t = u * 784 + n0 + sl;
            size_t dstb = ((size_t)b * 6272 + t) * 256 + cibase;
#pragma unroll
            for (int q = 0; q < 16; q++) {
                float v = smf[(q * 8 + u) * 113 + sl];
                split_store(v, thetat_hi, thetat_lo, dstb + q);
            }
        }
    } else {
        // g/phi: 2x2 pool -> [b][ci][p], ci = cibase + (cc>>3), p = (cc&7)*196 + sp
        __nv_bfloat16* hi = (region == 1) ? gp_hi : pp_hi;
        __nv_bfloat16* lo = (region == 1) ? gp_lo : pp_lo;
        if (tid < 128) {
            int cc = tid;
            int ci = cibase + (cc >> 3);
            int p0 = (cc & 7) * 196;
            size_t base = ((size_t)b * 256 + ci) * 1568 + p0;
#pragma unroll
            for (int pr = 0; pr < 2; pr++) {
                int sp = (2 * blockIdx.x + pr) * 14;
#pragma unroll
                for (int pc = 0; pc < 14; pc++) {
                    const float* p = &smf[cc * 113 + pr * 56 + pc * 2];
                    float v = fmaxf(fmaxf(p[0], p[1]), fmaxf(p[28], p[29]));
                    split_store(v, hi, lo, base + sp + pc);
                }
            }
        }
    }
}

// ====================== z GEMM: z = wW @ yt^T + bW ======================
template <int KDIM>
__global__ __launch_bounds__(256, 1) void mma_conv_gemm(
    const __nv_bfloat16* __restrict__ Ahi, const __nv_bfloat16* __restrict__ Alo,
    const __nv_bfloat16* __restrict__ Bhi, const __nv_bfloat16* __restrict__ Blo,
    float* __restrict__ outb, const float* __restrict__ biasb)
{
    constexpr int KITERS = KDIM / 32;
    extern __shared__ __align__(128) __nv_bfloat16 smem[];
    const uint32_t smem_base = smem_to_u32(smem);

    const int tid = threadIdx.x;
    const int lane = tid & 31;
    const int wid = tid >> 5;
    const int warp_m = wid & 3;
    const int warp_n = wid >> 2;
    const int img = blockIdx.z;
    const int m0 = blockIdx.y * 128;
    const int n0 = blockIdx.x * 112;

    const __nv_bfloat16* A_hi = Ahi + (size_t)m0 * KDIM;
    const __nv_bfloat16* A_lo = Alo + (size_t)m0 * KDIM;
    const __nv_bfloat16* B_hi = Bhi + ((size_t)img * 784 + n0) * KDIM;
    const __nv_bfloat16* B_lo = Blo + ((size_t)img * 784 + n0) * KDIM;

    auto load_stage = [&](int st, int k0) {
        const uint32_t sb = smem_base + (uint32_t)(st * STAGE_ELEMS * 2);
        for (int i = tid; i < 1920; i += 256) {
            int row, kc;
            const __nv_bfloat16* src;
            int dst_row;
            if (i < 1024) {
                int d = i >> 9, j = i & 511;
                row = j >> 2; kc = j & 3;
                src = (d ? A_lo : A_hi) + (size_t)row * KDIM + k0 + kc * 8;
                dst_row = d * 128 + row;
            } else {
                int j = i - 1024;
                int d = (j >= 448); if (d) j -= 448;
                row = j >> 2; kc = j & 3;
                src = (d ? B_lo : B_hi) + (size_t)row * KDIM + k0 + kc * 8;
                dst_row = 256 + d * 112 + row;
            }
            uint32_t dst = sb + (uint32_t)((dst_row * 40 + kc * 8) * 2);
            CP_ASYNC16(dst, src);
        }
    };

    float acc[2][7][4];
#pragma unroll
    for (int mi = 0; mi < 2; mi++)
#pragma unroll
        for (int ni = 0; ni < 7; ni++)
#pragma unroll
            for (int r = 0; r < 4; r++) acc[mi][ni][r] = 0.f;

#pragma unroll
    for (int s = 0; s < TC_STAGES - 1; s++) { load_stage(s, s * 32); CP_COMMIT(); }

    const int a_row = lane & 15, a_kh = lane >> 4;
    const int b_row = lane & 7,  b_kh = (lane >> 3) & 1;

    for (int it = 0; it < KITERS; it++) {
        CP_WAIT(TC_STAGES - 2);
        __syncthreads();
        if (it + TC_STAGES - 1 < KITERS)
            load_stage((it + TC_STAGES - 1) % TC_STAGES, (it + TC_STAGES - 1) * 32);
        CP_COMMIT();

        const uint32_t sb = smem_base + (uint32_t)((it % TC_STAGES) * STAGE_ELEMS * 2);
#pragma unroll
        for (int ks = 0; ks < 2; ks++) {
            uint32_t af[2][2][4];
#pragma unroll
            for (int d = 0; d < 2; d++)
#pragma unroll
                for (int mi = 0; mi < 2; mi++) {
                    int r = d * 128 + warp_m * 32 + mi * 16 + a_row;
                    int c = ks * 16 + a_kh * 8;
                    ldsm_x4(af[d][mi], sb + (uint32_t)((r * 40 + c) * 2));
                }
            uint32_t bf[2][7][2];
#pragma unroll
            for (int d = 0; d < 2; d++)
#pragma unroll
                for (int ni = 0; ni < 7; ni++) {
                    int r = 256 + d * 112 + warp_n * 56 + ni * 8 + b_row;
                    int c = ks * 16 + b_kh * 8;
                    ldsm_x2(bf[d][ni], sb + (uint32_t)((r * 40 + c) * 2));
                }
#pragma unroll
            for (int mi = 0; mi < 2; mi++)
#pragma unroll
                for (int ni = 0; ni < 7; ni++) {
                    mma_16816(acc[mi][ni], af[0][mi], bf[0][ni]);
                    mma_16816(acc[mi][ni], af[0][mi], bf[1][ni]);
                    mma_16816(acc[mi][ni], af[1][mi], bf[0][ni]);
                }
        }
        __syncthreads();
    }

    float* outp = outb + (size_t)img * 512 * 784 + (size_t)m0 * 784;
#pragma unroll
    for (int mi = 0; mi < 2; mi++) {
        int r0 = warp_m * 32 + mi * 16 + (lane >> 2);
        float bv0 = biasb[m0 + r0];
        float bv1 = biasb[m0 + r0 + 8];
#pragma unroll
        for (int ni = 0; ni < 7; ni++) {
            int col = n0 + warp_n * 56 + ni * 8 + (lane & 3) * 2;
            float2 v0 = make_float2(acc[mi][ni][0] + bv0, acc[mi][ni][1] + bv0);
            float2 v1 = make_float2(acc[mi][ni][2] + bv1, acc[mi][ni][3] + bv1);
            *reinterpret_cast<float2*>(outp + (size_t)r0 * 784 + col) = v0;
            *reinterpret_cast<float2*>(outp + (size_t)(r0 + 8) * 784 + col) = v1;
        }
    }
}

// ====================== square-tile mma mainloop (128x128, BK=32, 3 stages) ======
static constexpr int SQ_STAGES = 3;
static constexpr int SQ_STAGE_ELEMS = 512 * 40;
static constexpr int SQ_SMEM = SQ_STAGES * SQ_STAGE_ELEMS * 2;   // 122880

#define SQ_MAINLOOP(AHI, ALO, BHI, BLO, LDA, LDB, KITERS)                         \
    auto load_stage = [&](int st, int k0) {                                        \
        const uint32_t sb = smem_base + (uint32_t)(st * SQ_STAGE_ELEMS * 2);       \
        for (int i = tid; i < 2048; i += 256) {                                    \
            int row = i >> 2, kc = i & 3;                                          \
            const __nv_bfloat16* src;                                              \
            if (row < 128)      src = (AHI) + (size_t)row * (LDA) + k0 + kc * 8;   \
            else if (row < 256) src = (ALO) + (size_t)(row-128) * (LDA) + k0 + kc*8;\
            else if (row < 384) src = (BHI) + (size_t)(row-256) * (LDB) + k0 + kc*8;\
            else                src = (BLO) + (size_t)(row-384) * (LDB) + k0 + kc*8;\
            CP_ASYNC16(sb + (uint32_t)((row * 40 + kc * 8) * 2), src);             \
        }                                                                          \
    };                                                                             \
    float acc[2][8][4];                                                            \
    _Pragma("unroll") for (int mi = 0; mi < 2; mi++)                               \
    _Pragma("unroll") for (int ni = 0; ni < 8; ni++)                               \
    _Pragma("unroll") for (int r = 0; r < 4; r++) acc[mi][ni][r] = 0.f;            \
    _Pragma("unroll") for (int s = 0; s < SQ_STAGES - 1; s++) {                    \
        load_stage(s, s * 32); CP_COMMIT(); }                                      \
    const int a_row = lane & 15, a_kh = lane >> 4;                                 \
    const int b_row = lane & 7,  b_kh = (lane >> 3) & 1;                           \
    for (int it = 0; it < (KITERS); it++) {                                        \
        CP_WAIT(SQ_STAGES - 2);                                                    \
        __syncthreads();                                                           \
        if (it + SQ_STAGES - 1 < (KITERS))                                         \
            load_stage((it + SQ_STAGES - 1) % SQ_STAGES, (it + SQ_STAGES - 1)*32); \
        CP_COMMIT();                                                               \
        const uint32_t sb = smem_base + (uint32_t)((it % SQ_STAGES) * SQ_STAGE_ELEMS * 2); \
        _Pragma("unroll") for (int ks = 0; ks < 2; ks++) {                         \
            uint32_t af[2][2][4];                                                  \
            _Pragma("unroll") for (int d = 0; d < 2; d++)                          \
            _Pragma("unroll") for (int mi = 0; mi < 2; mi++) {                     \
                int r = d * 128 + warp_m * 32 + mi * 16 + a_row;                   \
                int c = ks * 16 + a_kh * 8;                                        \
                ldsm_x4(af[d][mi], sb + (uint32_t)((r * 40 + c) * 2));             \
            }                                                                      \
            uint32_t bfr[2][8][2];                                                 \
            _Pragma("unroll") for (int d = 0; d < 2; d++)                          \
            _Pragma("unroll") for (int ni = 0; ni < 8; ni++) {                     \
                int r = 256 + d * 128 + warp_n * 64 + ni * 8 + b_row;              \
                int c = ks * 16 + b_kh * 8;                                        \
                ldsm_x2(bfr[d][ni], sb + (uint32_t)((r * 40 + c) * 2));            \
            }                                                                      \
            _Pragma("unroll") for (int mi = 0; mi < 2; mi++)                       \
            _Pragma("unroll") for (int ni = 0; ni < 8; ni++) {                     \
                mma_16816(acc[mi][ni], af[0][mi], bfr[0][ni]);                     \
                mma_16816(acc[mi][ni], af[0][mi], bfr[1][ni]);                     \
                mma_16816(acc[mi][ni], af[1][mi], bfr[0][ni]);                     \
            }                                                                      \
        }                                                                          \
        __syncthreads();                                                           \
    }

#define SQ_STORE_SMF(SCALE)                                                       \
    float* smf = reinterpret_cast<float*>(smem);                                   \
    _Pragma("unroll") for (int mi = 0; mi < 2; mi++) {                             \
        int r0 = warp_m * 32 + mi * 16 + (lane >> 2);                              \
        _Pragma("unroll") for (int ni = 0; ni < 8; ni++) {                         \
            int col = warp_n * 64 + ni * 8 + (lane & 3) * 2;                       \
            smf[r0 * 129 + col]           = acc[mi][ni][0] * (SCALE);              \
            smf[r0 * 129 + col + 1]       = acc[mi][ni][1] * (SCALE);              \
            smf[(r0 + 8) * 129 + col]     = acc[mi][ni][2] * (SCALE);              \
            smf[(r0 + 8) * 129 + col + 1] = acc[mi][ni][3] * (SCALE);              \
        }                                                                          \
    }                                                                              \
    __syncthreads();

// ---- M[ci][cg] = sum_p pp[b][ci][p] gp[b][cg][p] / 1568; stored Mt[b][cg][ci] ----
__global__ __launch_bounds__(256, 1) void mma_nt_M()
{
    extern __shared__ __align__(128) __nv_bfloat16 smem[];
    const uint32_t smem_base = smem_to_u32(smem);
    const int tid = threadIdx.x, lane = tid & 31, wid = tid >> 5;
    const int warp_m = wid & 3, warp_n = wid >> 2;
    const int b = blockIdx.z;
    const int i0 = blockIdx.y * 128;   // ci (phi)
    const int j0 = blockIdx.x * 128;   // cg (g)

    const __nv_bfloat16* A_hi = pp_hi + ((size_t)b * 256 + i0) * 1568;
    const __nv_bfloat16* A_lo = pp_lo + ((size_t)b * 256 + i0) * 1568;
    const __nv_bfloat16* B_hi = gp_hi + ((size_t)b * 256 + j0) * 1568;
    const __nv_bfloat16* B_lo = gp_lo + ((size_t)b * 256 + j0) * 1568;

    SQ_MAINLOOP(A_hi, A_lo, B_hi, B_lo, 1568, 1568, 49)
    SQ_STORE_SMF(1.0f / 1568.0f)

    // transpose store: Mt[(b*256 + j0+j)*256 + i0+i]
    {
        int j = tid >> 1, ih = (tid & 1) * 64;
        size_t base = ((size_t)b * 256 + j0 + j) * 256 + i0 + ih;
#pragma unroll 8
        for (int i = 0; i < 64; i++) {
            float v = smf[(ih + i) * 129 + j];
            split_store(v, Mt_hi, Mt_lo, base + i);
        }
    }
}

// ---- y_v[t][cg] = sum_ci thetat[b][t][ci] Mt[b][cg][ci]; scatter to yt conv layout ----
__global__ __launch_bounds__(256, 1) void mma_tn_y()
{
    extern __shared__ __align__(128) __nv_bfloat16 smem[];
    const uint32_t smem_base = smem_to_u32(smem);
    const int tid = threadIdx.x, lane = tid & 31, wid = tid >> 5;
    const int warp_m = wid & 3, warp_n = wid >> 2;
    const int b = blockIdx.z;
    const int m0 = blockIdx.y * 128;   // t
    const int n0 = blockIdx.x * 128;   // cg

    const __nv_bfloat16* A_hi = thetat_hi + ((size_t)b * 6272 + m0) * 256;
    const __nv_bfloat16* A_lo = thetat_lo + ((size_t)b * 6272 + m0) * 256;
    const __nv_bfloat16* B_hi = Mt_hi + ((size_t)b * 256 + n0) * 256;
    const __nv_bfloat16* B_lo = Mt_lo + ((size_t)b * 256 + n0) * 256;

    SQ_MAINLOOP(A_hi, A_lo, B_hi, B_lo, 256, 256, 8)
    SQ_STORE_SMF(1.0f)

    // view->conv: img = 8b + (cg>>5), c = (cg&31)*8 + t/784, s = t%784
    {
        int tt = tid >> 1, nh = (tid & 1) * 64;
        int tg = m0 + tt;
        int tq = tg / 784, s = tg % 784;
#pragma unroll 8
        for (int nn = 0; nn < 64; nn++) {
            int n = n0 + nh + nn;
            float v = smf[tt * 129 + nh + nn];
            size_t dst = ((size_t)(8 * b + (n >> 5)) * 784 + s) * 256 + ((n & 31) * 8 + tq);
            split_store(v, yt_hi, yt_lo, dst);
        }
    }
}

// ====================== BN stats + BN/residual ======================
__global__ __launch_bounds__(256) void bn_stats()
{
    const int c = blockIdx.x;
    float s1 = 0.f, s2 = 0.f;
    const float* base = z_buf + c * 784;
    for (int n = 0; n < 64; n++) {
        const float* p = base + n * 401408;
        for (int s = threadIdx.x; s < 784; s += 256) {
            float v = p[s];
            s1 += v; s2 += v * v;
        }
    }
    __shared__ float r1[256], r2[256];
    r1[threadIdx.x] = s1; r2[threadIdx.x] = s2;
    __syncthreads();
    for (int off = 128; off > 0; off >>= 1) {
        if (threadIdx.x < off) {
            r1[threadIdx.x] += r1[threadIdx.x + off];
            r2[threadIdx.x] += r2[threadIdx.x + off];
        }
        __syncthreads();
    }
    if (threadIdx.x == 0) { g_stats[c] = r1[0]; g_stats[512 + c] = r2[0]; }
}

__global__ __launch_bounds__(256) void bn_res(
    const float* __restrict__ x,
    const float* __restrict__ gamma, const float* __restrict__ beta,
    float* __restrict__ out)
{
    const int i4 = blockIdx.x * 256 + threadIdx.x;
    const int c = (i4 / 196) & 511;
    const float inv_cnt = 1.0f / 50176.0f;
    float mean = g_stats[c] * inv_cnt;
    float var  = g_stats[512 + c] * inv_cnt - mean * mean;
    float sc = gamma[c] * rsqrtf(var + 1e-5f);
    float sh = beta[c] - mean * sc;
    float4 zv = reinterpret_cast<const float4*>(z_buf)[i4];
    float4 xv = reinterpret_cast<const float4*>(x)[i4];
    float4 o;
    o.x = zv.x * sc + sh + xv.x;
    o.y = zv.y * sc + sh + xv.y;
    o.z = zv.z * sc + sh + xv.z;
    o.w = zv.w * sc + sh + xv.w;
    reinterpret_cast<float4*>(out)[i4] = o;
}

// ====================== launcher ======================
extern "C" void kernel_launch(void* const* d_in, const int* in_sizes, int n_in,
                              void* d_out, int out_size)
{
    const float* x     = (const float*)d_in[0];
    const float* wg    = (const float*)d_in[1];
    const float* bg    = (const float*)d_in[2];
    const float* wth   = (const float*)d_in[3];
    const float* bth   = (const float*)d_in[4];
    const float* wph   = (const float*)d_in[5];
    const float* bph   = (const float*)d_in[6];
    const float* wW    = (const float*)d_in[7];
    const float* bW    = (const float*)d_in[8];
    const float* gamma = (const float*)d_in[9];
    const float* beta  = (const float*)d_in[10];
    float* out = (float*)d_out;

    cudaFuncSetAttribute(proj_gemm_mma,
                         cudaFuncAttributeMaxDynamicSharedMemorySize, TC_SMEM);
    cudaFuncSetAttribute(mma_conv_gemm<256>,
                         cudaFuncAttributeMaxDynamicSharedMemorySize, TC_SMEM);
    cudaFuncSetAttribute(mma_nt_M,
                         cudaFuncAttributeMaxDynamicSharedMemorySize, SQ_SMEM);
    cudaFuncSetAttribute(mma_tn_y,
                         cudaFuncAttributeMaxDynamicSharedMemorySize, SQ_SMEM);

    __nv_bfloat16 *p_wW_hi, *p_wW_lo, *p_yt_hi, *p_yt_lo;
    float *p_z;
    cudaGetSymbolAddress((void**)&p_wW_hi, wW_hi);
    cudaGetSymbolAddress((void**)&p_wW_lo, wW_lo);
    cudaGetSymbolAddress((void**)&p_yt_hi, yt_hi);
    cudaGetSymbolAddress((void**)&p_yt_lo, yt_lo);
    cudaGetSymbolAddress((void**)&p_z, z_buf);

    split_w_kernel<<<2048, 256>>>(wth, wg, wph, wW);
    split_x_kernel<<<dim3(49, 32, 64), dim3(16, 16)>>>(x);

    proj_gemm_mma<<<dim3(7, 6, 64), 256, TC_SMEM>>>(bth, bg, bph);

    mma_nt_M<<<dim3(2, 2, 8), 256, SQ_SMEM>>>();
    mma_tn_y<<<dim3(2, 49, 8), 256, SQ_SMEM>>>();

    mma_conv_gemm<256><<<dim3(7, 4, 64), 256, TC_SMEM>>>(
        p_wW_hi, p_wW_lo, p_yt_hi, p_yt_lo, p_z, bW);

    bn_stats<<<512, 256>>>();
    bn_res<<<25088, 256>>>(x, gamma, beta, out);
}

// round 6
// speedup vs baseline: 1.1825x; 1.1825x over previous
#include <cuda_runtime.h>
#include <cuda_bf16.h>
#include <cstdint>

// ====================== mma.sync helpers ======================
__device__ __forceinline__ uint32_t smem_to_u32(const void* smem_ptr) {
    uint32_t addr;
    asm("{ .reg .u64 tmp; cvta.to.shared.u64 tmp, %1; cvt.u32.u64 %0, tmp; }"
        : "=r"(addr) : "l"(smem_ptr));
    return addr;
}
__device__ __forceinline__ void ldsm_x4(uint32_t* r, uint32_t addr) {
    asm volatile("ldmatrix.sync.aligned.m8n8.x4.shared.b16 {%0,%1,%2,%3}, [%4];"
        : "=r"(r[0]), "=r"(r[1]), "=r"(r[2]), "=r"(r[3]) : "r"(addr));
}
__device__ __forceinline__ void ldsm_x2(uint32_t* r, uint32_t addr) {
    asm volatile("ldmatrix.sync.aligned.m8n8.x2.shared.b16 {%0,%1}, [%2];"
        : "=r"(r[0]), "=r"(r[1]) : "r"(addr));
}
__device__ __forceinline__ void mma_16816(float* c, const uint32_t* a, const uint32_t* b) {
    asm volatile("mma.sync.aligned.m16n8k16.row.col.f32.bf16.bf16.f32 "
        "{%0,%1,%2,%3}, {%4,%5,%6,%7}, {%8,%9}, {%0,%1,%2,%3};"
        : "+f"(c[0]), "+f"(c[1]), "+f"(c[2]), "+f"(c[3])
        : "r"(a[0]), "r"(a[1]), "r"(a[2]), "r"(a[3]), "r"(b[0]), "r"(b[1]));
}
#define CP_ASYNC16(dst, src) \
    asm volatile("cp.async.cg.shared.global [%0], [%1], 16;" :: "r"(dst), "l"(src))
#define CP_COMMIT() asm volatile("cp.async.commit_group;" ::: "memory")
#define CP_WAIT(n)  asm volatile("cp.async.wait_group %0;" :: "n"(n) : "memory")

// Shared compute stage: A rows [0,256), B rows [256, 256+2*BD). NF = n8-frags/warp.
// bf16x3: hi*hi + hi*lo + lo*hi.
template <int NF, int BD>
__device__ __forceinline__ void mma_compute_stage(uint32_t sb, int warp_m, int warp_n,
                                                  int lane, float (*acc)[4])
{
    const int a_row = lane & 15, a_kh = lane >> 4;
#pragma unroll
    for (int ks = 0; ks < 2; ks++) {
        uint32_t af[2][2][4];
#pragma unroll
        for (int d = 0; d < 2; d++)
#pragma unroll
            for (int mi = 0; mi < 2; mi++) {
                int r = d * 128 + warp_m * 32 + mi * 16 + a_row;
                int c = ks * 16 + a_kh * 8;
                ldsm_x4(af[d][mi], sb + (uint32_t)((r * 40 + c) * 2));
            }
        uint32_t bq[2][(NF + 1) / 2][4];
#pragma unroll
        for (int d = 0; d < 2; d++) {
#pragma unroll
            for (int np = 0; np < NF / 2; np++) {
                int r = 256 + d * BD + warp_n * (NF * 8) + np * 16 + (lane & 15);
                int c = ks * 16 + (lane >> 4) * 8;
                ldsm_x4(bq[d][np], sb + (uint32_t)((r * 40 + c) * 2));
            }
            if (NF & 1) {
                int r = 256 + d * BD + warp_n * (NF * 8) + (NF - 1) * 8 + (lane & 7);
                int c = ks * 16 + ((lane >> 3) & 1) * 8;
                ldsm_x2(bq[d][NF / 2], sb + (uint32_t)((r * 40 + c) * 2));
            }
        }
#pragma unroll
        for (int mi = 0; mi < 2; mi++)
#pragma unroll
            for (int ni = 0; ni < NF; ni++) {
                uint32_t fh[2], fl[2];
                if ((NF & 1) && ni == NF - 1) {
                    fh[0] = bq[0][NF / 2][0]; fh[1] = bq[0][NF / 2][1];
                    fl[0] = bq[1][NF / 2][0]; fl[1] = bq[1][NF / 2][1];
                } else {
                    fh[0] = bq[0][ni >> 1][ni & 1]; fh[1] = bq[0][ni >> 1][(ni & 1) + 2];
                    fl[0] = bq[1][ni >> 1][ni & 1]; fl[1] = bq[1][ni >> 1][(ni & 1) + 2];
                }
                mma_16816(acc[mi * NF + ni], af[0][mi], fh);
                mma_16816(acc[mi * NF + ni], af[0][mi], fl);
                mma_16816(acc[mi * NF + ni], af[1][mi], fh);
            }
    }
}

// ====================== static scratch ======================
__device__ float z_buf  [64 * 512 * 784];
__device__ float g_stats[1024];
__device__ float Mpart  [7 * 8 * 256 * 256];     // split-K partials

__device__ __nv_bfloat16 wcat_hi[768 * 512], wcat_lo[768 * 512];
__device__ __nv_bfloat16 wW_hi [512 * 256],  wW_lo [512 * 256];
__device__ __nv_bfloat16 xt_hi [64 * 784 * 512], xt_lo[64 * 784 * 512];   // x^T per img
__device__ __nv_bfloat16 thetat_hi[8 * 6272 * 256], thetat_lo[8 * 6272 * 256]; // [b][t][ci]
__device__ __nv_bfloat16 yt_hi [64 * 784 * 256], yt_lo[64 * 784 * 256];   // [img][s][c]
__device__ __nv_bfloat16 gp_hi [8 * 256 * 1568], gp_lo[8 * 256 * 1568];   // [b][ci][p]
__device__ __nv_bfloat16 pp_hi [8 * 256 * 1568], pp_lo[8 * 256 * 1568];
__device__ __nv_bfloat16 Mt_hi [8 * 256 * 256],  Mt_lo[8 * 256 * 256];    // [b][cg][ci]

__device__ __forceinline__ void split_store(float v, __nv_bfloat16* hi, __nv_bfloat16* lo,
                                            size_t idx) {
    __nv_bfloat16 h = __float2bfloat16(v);
    hi[idx] = h;
    lo[idx] = __float2bfloat16(v - __bfloat162float(h));
}

// ====================== split/convert kernels ======================
__global__ __launch_bounds__(256) void split_w_kernel(
    const float* __restrict__ wth, const float* __restrict__ wg,
    const float* __restrict__ wph, const float* __restrict__ wW)
{
    int i = blockIdx.x * 256 + threadIdx.x;
    if (i < 393216) {
        int r = i >> 9, k = i & 511;
        const float* w = (r < 256) ? wth : (r < 512) ? wg : wph;
        split_store(w[(r & 255) * 512 + k], wcat_hi, wcat_lo, i);
    } else {
        int j = i - 393216;
        split_store(wW[j], wW_hi, wW_lo, j);
    }
}

__global__ __launch_bounds__(256) void split_x_kernel(const float* __restrict__ x)
{
    __shared__ float t[16][17];
    int img = blockIdx.z;
    int c0 = blockIdx.y * 16, s0 = blockIdx.x * 16;
    const float* src = x + ((size_t)img * 512 + c0) * 784 + s0;
    t[threadIdx.y][threadIdx.x] = src[threadIdx.y * 784 + threadIdx.x];
    __syncthreads();
    float v = t[threadIdx.x][threadIdx.y];
    size_t dst = ((size_t)img * 784 + s0 + threadIdx.y) * 512 + c0 + threadIdx.x;
    split_store(v, xt_hi, xt_lo, dst);
}

// ====================== projection GEMM (theta|g|phi) ======================
static constexpr int TC_STAGES = 4;
static constexpr int STAGE_ELEMS = 480 * 40;
static constexpr int TC_SMEM = TC_STAGES * STAGE_ELEMS * 2;   // 153600

__global__ __launch_bounds__(256, 1) void proj_gemm_mma(
    const float* __restrict__ bth, const float* __restrict__ bg,
    const float* __restrict__ bph)
{
    constexpr int KDIM = 512;
    constexpr int KITERS = KDIM / 32;
    extern __shared__ __align__(128) __nv_bfloat16 smem[];
    const uint32_t smem_base = smem_to_u32(smem);

    const int tid = threadIdx.x;
    const int lane = tid & 31;
    const int wid = tid >> 5;
    const int warp_m = wid & 3;
    const int warp_n = wid >> 2;
    const int img = blockIdx.z;
    const int m0 = blockIdx.y * 128;
    const int n0 = blockIdx.x * 112;

    const __nv_bfloat16* A_hi = wcat_hi + (size_t)m0 * KDIM;
    const __nv_bfloat16* A_lo = wcat_lo + (size_t)m0 * KDIM;
    const __nv_bfloat16* B_hi = xt_hi + ((size_t)img * 784 + n0) * KDIM;
    const __nv_bfloat16* B_lo = xt_lo + ((size_t)img * 784 + n0) * KDIM;

    auto load_stage = [&](int st, int k0) {
        const uint32_t sb = smem_base + (uint32_t)(st * STAGE_ELEMS * 2);
        for (int i = tid; i < 1920; i += 256) {
            int row, kc;
            const __nv_bfloat16* src;
            int dst_row;
            if (i < 1024) {
                int d = i >> 9, j = i & 511;
                row = j >> 2; kc = j & 3;
                src = (d ? A_lo : A_hi) + (size_t)row * KDIM + k0 + kc * 8;
                dst_row = d * 128 + row;
            } else {
                int j = i - 1024;
                int d = (j >= 448); if (d) j -= 448;
                row = j >> 2; kc = j & 3;
                src = (d ? B_lo : B_hi) + (size_t)row * KDIM + k0 + kc * 8;
                dst_row = 256 + d * 112 + row;
            }
            uint32_t dst = sb + (uint32_t)((dst_row * 40 + kc * 8) * 2);
            CP_ASYNC16(dst, src);
        }
    };

    float acc[14][4];
#pragma unroll
    for (int q = 0; q < 14; q++)
#pragma unroll
        for (int r = 0; r < 4; r++) acc[q][r] = 0.f;

#pragma unroll
    for (int s = 0; s < TC_STAGES - 1; s++) { load_stage(s, s * 32); CP_COMMIT(); }

    for (int it = 0; it < KITERS; it++) {
        CP_WAIT(TC_STAGES - 2);
        __syncthreads();
        if (it + TC_STAGES - 1 < KITERS)
            load_stage((it + TC_STAGES - 1) % TC_STAGES, (it + TC_STAGES - 1) * 32);
        CP_COMMIT();
        const uint32_t sb = smem_base + (uint32_t)((it % TC_STAGES) * STAGE_ELEMS * 2);
        mma_compute_stage<7, 112>(sb, warp_m, warp_n, lane, acc);
        __syncthreads();
    }

    // ---- stage C + bias into SMEM fp32 [128 ch][pitch 113 spatial] ----
    const int region = m0 >> 8;             // 0 theta, 1 g, 2 phi
    const int mloc = m0 & 255;
    const float* bias = (region == 0) ? bth : (region == 1) ? bg : bph;
    float* smf = reinterpret_cast<float*>(smem);

#pragma unroll
    for (int mi = 0; mi < 2; mi++) {
        int r0 = warp_m * 32 + mi * 16 + (lane >> 2);
        float bv0 = bias[mloc + r0];
        float bv1 = bias[mloc + r0 + 8];
#pragma unroll
        for (int ni = 0; ni < 7; ni++) {
            int col = warp_n * 56 + ni * 8 + (lane & 3) * 2;
            smf[r0 * 113 + col]           = acc[mi * 7 + ni][0] + bv0;
            smf[r0 * 113 + col + 1]       = acc[mi * 7 + ni][1] + bv0;
            smf[(r0 + 8) * 113 + col]     = acc[mi * 7 + ni][2] + bv1;
            smf[(r0 + 8) * 113 + col + 1] = acc[mi * 7 + ni][3] + bv1;
        }
    }
    __syncthreads();

    const int b = img >> 3, r = img & 7;
    const int cibase = r * 32 + (mloc >> 3);

    if (region == 0) {
        // theta -> thetat[b][t][ci], t = u*784 + (n0+sl), ci = cibase + q
        for (int item = tid; item < 896; item += 256) {
            int sl = item >> 3, u = item & 7;
            int t = u * 784 + n0 + sl;
            size_t dstb = ((size_t)b * 6272 + t) * 256 + cibase;
#pragma unroll
            for (int q = 0; q < 16; q++) {
                float v = smf[(q * 8 + u) * 113 + sl];
                split_store(v, thetat_hi, thetat_lo, dstb + q);
            }
        }
    } else {
        // g/phi: 2x2 pool -> [b][ci][p], ci = cibase + (cc>>3), p = (cc&7)*196 + sp
        __nv_bfloat16* hi = (region == 1) ? gp_hi : pp_hi;
        __nv_bfloat16* lo = (region == 1) ? gp_lo : pp_lo;
        if (tid < 128) {
            int cc = tid;
            int ci = cibase + (cc >> 3);
            int p0 = (cc & 7) * 196;
            size_t base = ((size_t)b * 256 + ci) * 1568 + p0;
#pragma unroll
            for (int pr = 0; pr < 2; pr++) {
                int sp = (2 * blockIdx.x + pr) * 14;
#pragma unroll
                for (int pc = 0; pc < 14; pc++) {
                    const float* p = &smf[cc * 113 + pr * 56 + pc * 2];
                    float v = fmaxf(fmaxf(p[0], p[1]), fmaxf(p[28], p[29]));
                    split_store(v, hi, lo, base + sp + pc);
                }
            }
        }
    }
}

// ====================== z GEMM: z = wW @ yt^T + bW ======================
__global__ __launch_bounds__(256, 1) void mma_z_gemm(const float* __restrict__ biasb)
{
    constexpr int KDIM = 256;
    constexpr int KITERS = KDIM / 32;
    extern __shared__ __align__(128) __nv_bfloat16 smem[];
    const uint32_t smem_base = smem_to_u32(smem);

    const int tid = threadIdx.x;
    const int lane = tid & 31;
    const int wid = tid >> 5;
    const int warp_m = wid & 3;
    const int warp_n = wid >> 2;
    const int img = blockIdx.z;
    const int m0 = blockIdx.y * 128;
    const int n0 = blockIdx.x * 112;

    const __nv_bfloat16* A_hi = wW_hi + (size_t)m0 * KDIM;
    const __nv_bfloat16* A_lo = wW_lo + (size_t)m0 * KDIM;
    const __nv_bfloat16* B_hi = yt_hi + ((size_t)img * 784 + n0) * KDIM;
    const __nv_bfloat16* B_lo = yt_lo + ((size_t)img * 784 + n0) * KDIM;

    auto load_stage = [&](int st, int k0) {
        const uint32_t sb = smem_base + (uint32_t)(st * STAGE_ELEMS * 2);
        for (int i = tid; i < 1920; i += 256) {
            int row, kc;
            const __nv_bfloat16* src;
            int dst_row;
            if (i < 1024) {
                int d = i >> 9, j = i & 511;
                row = j >> 2; kc = j & 3;
                src = (d ? A_lo : A_hi) + (size_t)row * KDIM + k0 + kc * 8;
                dst_row = d * 128 + row;
            } else {
                int j = i - 1024;
                int d = (j >= 448); if (d) j -= 448;
                row = j >> 2; kc = j & 3;
                src = (d ? B_lo : B_hi) + (size_t)row * KDIM + k0 + kc * 8;
                dst_row = 256 + d * 112 + row;
            }
            uint32_t dst = sb + (uint32_t)((dst_row * 40 + kc * 8) * 2);
            CP_ASYNC16(dst, src);
        }
    };

    float acc[14][4];
#pragma unroll
    for (int q = 0; q < 14; q++)
#pragma unroll
        for (int r = 0; r < 4; r++) acc[q][r] = 0.f;

#pragma unroll
    for (int s = 0; s < TC_STAGES - 1; s++) { load_stage(s, s * 32); CP_COMMIT(); }

    for (int it = 0; it < KITERS; it++) {
        CP_WAIT(TC_STAGES - 2);
        __syncthreads();
        if (it + TC_STAGES - 1 < KITERS)
            load_stage((it + TC_STAGES - 1) % TC_STAGES, (it + TC_STAGES - 1) * 32);
        CP_COMMIT();
        const uint32_t sb = smem_base + (uint32_t)((it % TC_STAGES) * STAGE_ELEMS * 2);
        mma_compute_stage<7, 112>(sb, warp_m, warp_n, lane, acc);
        __syncthreads();
    }

    float* outp = z_buf + (size_t)img * 512 * 784 + (size_t)m0 * 784;
#pragma unroll
    for (int mi = 0; mi < 2; mi++) {
        int r0 = warp_m * 32 + mi * 16 + (lane >> 2);
        float bv0 = biasb[m0 + r0];
        float bv1 = biasb[m0 + r0 + 8];
#pragma unroll
        for (int ni = 0; ni < 7; ni++) {
            int col = n0 + warp_n * 56 + ni * 8 + (lane & 3) * 2;
            float2 v0 = make_float2(acc[mi * 7 + ni][0] + bv0, acc[mi * 7 + ni][1] + bv0);
            float2 v1 = make_float2(acc[mi * 7 + ni][2] + bv1, acc[mi * 7 + ni][3] + bv1);
            *reinterpret_cast<float2*>(outp + (size_t)r0 * 784 + col) = v0;
            *reinterpret_cast<float2*>(outp + (size_t)(r0 + 8) * 784 + col) = v1;
        }
    }
}

// ====================== split-K nt_M: Mpart[sl][b] += Phi_tile @ G_tile^T ======
static constexpr int SQ_STAGES = 3;
static constexpr int SQ_STAGE_ELEMS = 512 * 40;
static constexpr int SQ_SMEM = SQ_STAGES * SQ_STAGE_ELEMS * 2;   // 122880

__global__ __launch_bounds__(256, 1) void mma_nt_M_split()
{
    extern __shared__ __align__(128) __nv_bfloat16 smem[];
    const uint32_t smem_base = smem_to_u32(smem);
    const int tid = threadIdx.x, lane = tid & 31, wid = tid >> 5;
    const int warp_m = wid & 3, warp_n = wid >> 2;
    const int b = blockIdx.z;
    const int sl = blockIdx.y;                    // K slice 0..6
    const int i0 = (blockIdx.x >> 1) * 128;       // ci (phi)
    const int j0 = (blockIdx.x & 1) * 128;        // cg (g)
    const int kbase = sl * 224;                   // 7 k-iters of 32

    const __nv_bfloat16* A_hi = pp_hi + ((size_t)b * 256 + i0) * 1568 + kbase;
    const __nv_bfloat16* A_lo = pp_lo + ((size_t)b * 256 + i0) * 1568 + kbase;
    const __nv_bfloat16* B_hi = gp_hi + ((size_t)b * 256 + j0) * 1568 + kbase;
    const __nv_bfloat16* B_lo = gp_lo + ((size_t)b * 256 + j0) * 1568 + kbase;

    auto load_stage = [&](int st, int k0) {
        const uint32_t sb = smem_base + (uint32_t)(st * SQ_STAGE_ELEMS * 2);
        for (int i = tid; i < 2048; i += 256) {
            int row = i >> 2, kc = i & 3;
            const __nv_bfloat16* src;
            if (row < 128)      src = A_hi + (size_t)row * 1568 + k0 + kc * 8;
            else if (row < 256) src = A_lo + (size_t)(row - 128) * 1568 + k0 + kc * 8;
            else if (row < 384) src = B_hi + (size_t)(row - 256) * 1568 + k0 + kc * 8;
            else                src = B_lo + (size_t)(row - 384) * 1568 + k0 + kc * 8;
            CP_ASYNC16(sb + (uint32_t)((row * 40 + kc * 8) * 2), src);
        }
    };

    float acc[16][4];
#pragma unroll
    for (int q = 0; q < 16; q++)
#pragma unroll
        for (int r = 0; r < 4; r++) acc[q][r] = 0.f;

#pragma unroll
    for (int s = 0; s < SQ_STAGES - 1; s++) { load_stage(s, s * 32); CP_COMMIT(); }

    for (int it = 0; it < 7; it++) {
        CP_WAIT(SQ_STAGES - 2);
        __syncthreads();
        if (it + SQ_STAGES - 1 < 7)
            load_stage((it + SQ_STAGES - 1) % SQ_STAGES, (it + SQ_STAGES - 1) * 32);
        CP_COMMIT();
        const uint32_t sb = smem_base + (uint32_t)((it % SQ_STAGES) * SQ_STAGE_ELEMS * 2);
        mma_compute_stage<8, 128>(sb, warp_m, warp_n, lane, acc);
        __syncthreads();
    }

    float* outp = Mpart + ((size_t)(sl * 8 + b)) * 65536;
#pragma unroll
    for (int mi = 0; mi < 2; mi++) {
        int ri = i0 + warp_m * 32 + mi * 16 + (lane >> 2);
#pragma unroll
        for (int ni = 0; ni < 8; ni++) {
            int col = j0 + warp_n * 64 + ni * 8 + (lane & 3) * 2;
            *reinterpret_cast<float2*>(outp + (size_t)ri * 256 + col) =
                make_float2(acc[mi * 8 + ni][0], acc[mi * 8 + ni][1]);
            *reinterpret_cast<float2*>(outp + (size_t)(ri + 8) * 256 + col) =
                make_float2(acc[mi * 8 + ni][2], acc[mi * 8 + ni][3]);
        }
    }
}

// ---- reduce 7 partials, scale 1/1568, transpose -> Mt[b][cg][ci] bf16 split ----
__global__ __launch_bounds__(256) void reduce_M()
{
    int idx = blockIdx.x * 256 + threadIdx.x;     // 524288 total
    int b = idx >> 16, j = (idx >> 8) & 255, i = idx & 255;
    float s = 0.f;
#pragma unroll
    for (int sl = 0; sl < 7; sl++)
        s += Mpart[((size_t)(sl * 8 + b)) * 65536 + (size_t)i * 256 + j];
    split_store(s * (1.0f / 1568.0f), Mt_hi, Mt_lo, (size_t)idx);
}

// ---- tn_y: gathered M-tile {tq*784 + s0+si}, coalesced yt stores ----
__global__ __launch_bounds__(256, 1) void mma_tn_y()
{
    extern __shared__ __align__(128) __nv_bfloat16 smem[];
    const uint32_t smem_base = smem_to_u32(smem);
    const int tid = threadIdx.x, lane = tid & 31, wid = tid >> 5;
    const int warp_m = wid & 3, warp_n = wid >> 2;
    const int b = blockIdx.z;
    const int s0 = blockIdx.y * 16;     // spatial block
    const int n0 = blockIdx.x * 128;    // cg

    auto load_stage = [&](int st, int k0) {
        const uint32_t sb = smem_base + (uint32_t)(st * SQ_STAGE_ELEMS * 2);
        for (int i = tid; i < 2048; i += 256) {
            int row = i >> 2, kc = i & 3;
            const __nv_bfloat16* src;
            if (row < 256) {
                int d = row >> 7, rl = row & 127;
                int t = (rl >> 4) * 784 + s0 + (rl & 15);
                src = (d ? thetat_lo : thetat_hi) + ((size_t)b * 6272 + t) * 256 + k0 + kc * 8;
            } else {
                int rr = row - 256;
                int d = rr >> 7, j = rr & 127;
                src = (d ? Mt_lo : Mt_hi) + ((size_t)b * 256 + n0 + j) * 256 + k0 + kc * 8;
            }
            CP_ASYNC16(sb + (uint32_t)((row * 40 + kc * 8) * 2), src);
        }
    };

    float acc[16][4];
#pragma unroll
    for (int q = 0; q < 16; q++)
#pragma unroll
        for (int r = 0; r < 4; r++) acc[q][r] = 0.f;

#pragma unroll
    for (int s = 0; s < SQ_STAGES - 1; s++) { load_stage(s, s * 32); CP_COMMIT(); }

    for (int it = 0; it < 8; it++) {
        CP_WAIT(SQ_STAGES - 2);
        __syncthreads();
        if (it + SQ_STAGES - 1 < 8)
            load_stage((it + SQ_STAGES - 1) % SQ_STAGES, (it + SQ_STAGES - 1) * 32);
        CP_COMMIT();
        const uint32_t sb = smem_base + (uint32_t)((it % SQ_STAGES) * SQ_STAGE_ELEMS * 2);
        mma_compute_stage<8, 128>(sb, warp_m, warp_n, lane, acc);
        __syncthreads();
    }

    // stage to smem fp32 [128 rows (tq,si)][pitch 129 cols (cg)]
    float* smf = reinterpret_cast<float*>(smem);
#pragma unroll
    for (int mi = 0; mi < 2; mi++) {
        int r0 = warp_m * 32 + mi * 16 + (lane >> 2);
#pragma unroll
        for (int ni = 0; ni < 8; ni++) {
            int col = warp_n * 64 + ni * 8 + (lane & 3) * 2;
            smf[r0 * 129 + col]           = acc[mi * 8 + ni][0];
            smf[r0 * 129 + col + 1]       = acc[mi * 8 + ni][1];
            smf[(r0 + 8) * 129 + col]     = acc[mi * 8 + ni][2];
            smf[(r0 + 8) * 129 + col + 1] = acc[mi * 8 + ni][3];
        }
    }
    __syncthreads();

    // coalesced store: yt[img][s0+si][kk*8 .. kk*8+7] <- smf over tq
    for (int v = tid; v < 2048; v += 256) {
        int kk = v & 31;
        int si = (v >> 5) & 15;
        int ig = v >> 9;
        int col = ig * 32 + kk;
        int cg = n0 + col;
        int img = 8 * b + (cg >> 5);
        int c0 = (cg & 31) * 8;
        __nv_bfloat16 hv[8], lv[8];
#pragma unroll
        for (int tq = 0; tq < 8; tq++) {
            float xv = smf[(tq * 16 + si) * 129 + col];
            __nv_bfloat16 h = __float2bfloat16(xv);
            hv[tq] = h;
            lv[tq] = __float2bfloat16(xv - __bfloat162float(h));
        }
        size_t dst = ((size_t)img * 784 + s0 + si) * 256 + c0;
        *reinterpret_cast<uint4*>(yt_hi + dst) = *reinterpret_cast<uint4*>(hv);
        *reinterpret_cast<uint4*>(yt_lo + dst) = *reinterpret_cast<uint4*>(lv);
    }
}

// ====================== BN stats + BN/residual ======================
__global__ __launch_bounds__(256) void bn_stats()
{
    const int c = blockIdx.x;
    float s1 = 0.f, s2 = 0.f;
    const float* base = z_buf + c * 784;
    for (int n = 0; n < 64; n++) {
        const float* p = base + n * 401408;
        for (int s = threadIdx.x; s < 784; s += 256) {
            float v = p[s];
            s1 += v; s2 += v * v;
        }
    }
    __shared__ float r1[256], r2[256];
    r1[threadIdx.x] = s1; r2[threadIdx.x] = s2;
    __syncthreads();
    for (int off = 128; off > 0; off >>= 1) {
        if (threadIdx.x < off) {
            r1[threadIdx.x] += r1[threadIdx.x + off];
            r2[threadIdx.x] += r2[threadIdx.x + off];
        }
        __syncthreads();
    }
    if (threadIdx.x == 0) { g_stats[c] = r1[0]; g_stats[512 + c] = r2[0]; }
}

__global__ __launch_bounds__(256) void bn_res(
    const float* __restrict__ x,
    const float* __restrict__ gamma, const float* __restrict__ beta,
    float* __restrict__ out)
{
    const int i4 = blockIdx.x * 256 + threadIdx.x;
    const int c = (i4 / 196) & 511;
    const float inv_cnt = 1.0f / 50176.0f;
    float mean = g_stats[c] * inv_cnt;
    float var  = g_stats[512 + c] * inv_cnt - mean * mean;
    float sc = gamma[c] * rsqrtf(var + 1e-5f);
    float sh = beta[c] - mean * sc;
    float4 zv = reinterpret_cast<const float4*>(z_buf)[i4];
    float4 xv = reinterpret_cast<const float4*>(x)[i4];
    float4 o;
    o.x = zv.x * sc + sh + xv.x;
    o.y = zv.y * sc + sh + xv.y;
    o.z = zv.z * sc + sh + xv.z;
    o.w = zv.w * sc + sh + xv.w;
    reinterpret_cast<float4*>(out)[i4] = o;
}

// ====================== launcher ======================
extern "C" void kernel_launch(void* const* d_in, const int* in_sizes, int n_in,
                              void* d_out, int out_size)
{
    const float* x     = (const float*)d_in[0];
    const float* wg    = (const float*)d_in[1];
    const float* bg    = (const float*)d_in[2];
    const float* wth   = (const float*)d_in[3];
    const float* bth   = (const float*)d_in[4];
    const float* wph   = (const float*)d_in[5];
    const float* bph   = (const float*)d_in[6];
    const float* wW    = (const float*)d_in[7];
    const float* bW    = (const float*)d_in[8];
    const float* gamma = (const float*)d_in[9];
    const float* beta  = (const float*)d_in[10];
    float* out = (float*)d_out;

    cudaFuncSetAttribute(proj_gemm_mma,
                         cudaFuncAttributeMaxDynamicSharedMemorySize, TC_SMEM);
    cudaFuncSetAttribute(mma_z_gemm,
                         cudaFuncAttributeMaxDynamicSharedMemorySize, TC_SMEM);
    cudaFuncSetAttribute(mma_nt_M_split,
                         cudaFuncAttributeMaxDynamicSharedMemorySize, SQ_SMEM);
    cudaFuncSetAttribute(mma_tn_y,
                         cudaFuncAttributeMaxDynamicSharedMemorySize, SQ_SMEM);

    split_w_kernel<<<2048, 256>>>(wth, wg, wph, wW);
    split_x_kernel<<<dim3(49, 32, 64), dim3(16, 16)>>>(x);

    proj_gemm_mma<<<dim3(7, 6, 64), 256, TC_SMEM>>>(bth, bg, bph);

    mma_nt_M_split<<<dim3(4, 7, 8), 256, SQ_SMEM>>>();
    reduce_M<<<2048, 256>>>();
    mma_tn_y<<<dim3(2, 49, 8), 256, SQ_SMEM>>>();

    mma_z_gemm<<<dim3(7, 4, 64), 256, TC_SMEM>>>(bW);

    bn_stats<<<512, 256>>>();
    bn_res<<<25088, 256>>>(x, gamma, beta, out);
}